// round 13
// baseline (speedup 1.0000x reference)
#include <cuda_runtime.h>
#include <cuda_bf16.h>

#define NN 16384
#define DIM 32
#define OUTD 16
#define BN_EPS 1e-5f

#define SCAN_GRID    1036         // 7 CTAs/SM x 148 SMs
#define SCAN_THREADS 128
#define SCAN_WARPS   4
#define DEPTH        4            // 32 KB ring -> 7 CTAs fit 228 KB smem
#define STAGE_INT4   512          // 8 KB per stage
#define STAGE_BYTES  8192
#define TOTAL_STAGES 131072       // 2^26 int4 / 512

#define TAIL_CTAS    128          // <=148: co-resident, barrier-safe
#define TAIL_THREADS 256          // 2 threads per node (output split 16/16)
#define NBUCK        8            // contention-splitting factor

// Scratch (__device__ globals start zero; tail self-cleans each call)
__device__ float    g_agg[(size_t)NN * DIM];
__device__ __align__(16) float g_stats_part[NBUCK][2 * DIM]; // [b][0:32)=sum,[32:64)=sq
__device__ __align__(16) float g_pool_part[NBUCK][DIM];
__device__ unsigned g_arrive;
__device__ unsigned g_done;

// ---------------- PTX helpers ----------------
__device__ __forceinline__ unsigned smem_u32(const void* p) {
    return (unsigned)__cvta_generic_to_shared(p);
}
__device__ __forceinline__ void mbar_init(unsigned a, unsigned cnt) {
    asm volatile("mbarrier.init.shared.b64 [%0], %1;" :: "r"(a), "r"(cnt) : "memory");
}
__device__ __forceinline__ void mbar_expect_tx(unsigned a, unsigned bytes) {
    asm volatile("mbarrier.arrive.expect_tx.shared.b64 _, [%0], %1;"
                 :: "r"(a), "r"(bytes) : "memory");
}
__device__ __forceinline__ void mbar_arrive(unsigned a) {
    asm volatile("mbarrier.arrive.shared.b64 _, [%0];" :: "r"(a) : "memory");
}
__device__ __forceinline__ void mbar_wait(unsigned a, unsigned phase) {
    asm volatile(
        "{\n\t.reg .pred P;\n\t"
        "WL_%=:\n\t"
        "mbarrier.try_wait.parity.acquire.cta.shared::cta.b64 P, [%0], %1, 0x989680;\n\t"
        "@P bra.uni WD_%=;\n\t"
        "bra.uni WL_%=;\n\t"
        "WD_%=:\n\t}"
        :: "r"(a), "r"(phase) : "memory");
}
__device__ __forceinline__ void bulk_g2s(unsigned dst, const void* src,
                                         unsigned bytes, unsigned mbar) {
    asm volatile(
        "cp.async.bulk.shared::cluster.global.mbarrier::complete_tx::bytes "
        "[%0], [%1], %2, [%3];"
        :: "r"(dst), "l"(src), "r"(bytes), "r"(mbar) : "memory");
}
__device__ __forceinline__ void red_add_v4(float* p, float a, float b, float c, float d) {
    asm volatile("red.global.add.v4.f32 [%0], {%1, %2, %3, %4};"
                 :: "l"(p), "f"(a), "f"(b), "f"(c), "f"(d) : "memory");
}
__device__ __forceinline__ void red_add_f32(float* p, float a) {
    asm volatile("red.global.add.f32 [%0], %1;" :: "l"(p), "f"(a) : "memory");
}
__device__ __forceinline__ unsigned ld_acq(const unsigned* p) {
    unsigned v;
    asm volatile("ld.acquire.gpu.u32 %0, [%1];" : "=r"(v) : "l"(p) : "memory");
    return v;
}
__device__ __forceinline__ void prefetch_l2(const void* p) {
    asm volatile("prefetch.global.L2 [%0];" :: "l"(p));
}

// ---------------------------------------------------------------------------
// K1: TMA-pipelined streaming scan of adj + v4-atomic scatter of nonzeros.
// 1036 CTAs = 7/SM; 224 KB smem/SM of in-flight TMA ring.
// ---------------------------------------------------------------------------
__global__ __launch_bounds__(SCAN_THREADS, 7) void k_scan(
    const char*  __restrict__ Ag,
    const float* __restrict__ x)
{
    __shared__ __align__(128) int4 buf[DEPTH][STAGE_INT4];
    __shared__ __align__(8) unsigned long long mbar[2 * DEPTH];

    const int tid  = threadIdx.x;
    const int lane = tid & 31;
    const int bid  = blockIdx.x;

    unsigned mb0 = smem_u32(mbar);
    #define FULL(d)  (mb0 + (unsigned)(d) * 16u)
    #define EMPTY(d) (mb0 + (unsigned)(d) * 16u + 8u)

    if (tid == 0) {
        #pragma unroll
        for (int d = 0; d < DEPTH; ++d) {
            mbar_init(FULL(d), 1);
            mbar_init(EMPTY(d), SCAN_WARPS);
        }
    }
    __syncthreads();

    // Warm x (2 MB = 131072 float4) into L2, overlapped with ring fill
    {
        const int t = bid * SCAN_THREADS + tid;
        if (t < 65536) {
            prefetch_l2((const float4*)x + t);
            prefetch_l2((const float4*)x + t + 65536);
        }
    }

    const int cnt = (TOTAL_STAGES - bid + SCAN_GRID - 1) / SCAN_GRID;  // 126-127

    if (tid == 0) {
        int pre = cnt < DEPTH ? cnt : DEPTH;
        for (int k = 0; k < pre; ++k) {
            int s = bid + k * SCAN_GRID;
            mbar_expect_tx(FULL(k), STAGE_BYTES);
            bulk_g2s(smem_u32(buf[k]), Ag + (size_t)s * STAGE_BYTES,
                     STAGE_BYTES, FULL(k));
        }
    }

    int slot = 0;
    unsigned ph = 0;
    for (int k = 0; k < cnt; ++k) {
        mbar_wait(FULL(slot), ph);

        const unsigned s = (unsigned)(bid + k * SCAN_GRID);
        #pragma unroll
        for (int u = 0; u < 4; ++u) {
            const int idx = tid + u * SCAN_THREADS;
            int4 v = buf[slot][idx];
            if ((v.x | v.y) | (v.z | v.w)) {
                const unsigned flat = s * STAGE_INT4 + (unsigned)idx;
                const unsigned j    = flat >> 12;            // 4096 int4 per adj row
                const unsigned c4   = (flat & 4095u) << 2;   // first of 4 columns
                const float* xr = x + ((size_t)j << 5);
                const int e[4] = {v.x, v.y, v.z, v.w};
                #pragma unroll
                for (int q = 0; q < 4; ++q) {
                    if (e[q]) {
                        const float sc = (float)e[q];
                        float* ar = g_agg + ((size_t)(c4 + q) << 5);
                        #pragma unroll
                        for (int d = 0; d < DIM; d += 4) {
                            float4 xv = __ldg((const float4*)(xr + d));
                            red_add_v4(ar + d, sc * xv.x, sc * xv.y,
                                               sc * xv.z, sc * xv.w);
                        }
                    }
                }
            }
        }

        __syncwarp();
        if (lane == 0) mbar_arrive(EMPTY(slot));          // 4 arrives, not 128

        if (tid == 0 && k + DEPTH < cnt) {
            mbar_wait(EMPTY(slot), ph);
            int s2 = bid + (k + DEPTH) * SCAN_GRID;
            mbar_expect_tx(FULL(slot), STAGE_BYTES);
            bulk_g2s(smem_u32(buf[slot]), Ag + (size_t)s2 * STAGE_BYTES,
                     STAGE_BYTES, FULL(slot));
        }
        if (++slot == DEPTH) { slot = 0; ph ^= 1u; }
    }
    #undef FULL
    #undef EMPTY
}

// ---------------------------------------------------------------------------
// K2 (tail): 128 CTAs x 256 threads; node pair-split 16/16; 8-way bucketed
// global reductions via DISTRIBUTED butterfly (31 shuffles for 32 values,
// lane l ends with the total of value l) + one scalar red per lane.
// ---------------------------------------------------------------------------
__global__ __launch_bounds__(TAIL_THREADS) void k_tail(
    const float* __restrict__ x,
    const float* __restrict__ W1,
    const float* __restrict__ b1,
    const float* __restrict__ gamma,
    const float* __restrict__ beta,
    const float* __restrict__ W2,
    const float* __restrict__ b2,
    const float* __restrict__ Wf,
    const float* __restrict__ bf,
    float*       __restrict__ out)
{
    __shared__ float sW1[DIM * DIM];     // W1 transposed: [o][d]
    __shared__ float sW2[DIM * DIM];     // W2 transposed: [o][d]
    __shared__ float sB1[DIM];
    __shared__ float sScale[DIM], sShift[DIM], sB2[DIM], sPool[DIM];
    __shared__ float sEx[128 * 33];      // r-exchange between node halves
    __shared__ int   sLast;

    const int tid   = threadIdx.x;
    const int lane  = tid & 31;
    const int nloc  = tid & 127;                 // node within CTA
    const int half  = tid >> 7;                  // 0 or 1
    const int obase = half * 16;                 // this thread's output range
    const int node  = blockIdx.x * 128 + nloc;
    const int buck  = blockIdx.x & (NBUCK - 1);

    if (tid < DIM) sB1[tid] = b1[tid];
    for (int k = tid; k < DIM * DIM; k += TAIL_THREADS) {
        int d = k >> 5, o = k & 31;
        sW1[o * DIM + d] = W1[k];
        sW2[o * DIM + d] = W2[k];
    }

    // v = x[node] + agg[node] -- both halves read; zeroing deferred
    float v[DIM];
    float4* ar = (float4*)(g_agg + ((size_t)node << 5));
    {
        const float4* xr = (const float4*)(x + ((size_t)node << 5));
        #pragma unroll
        for (int q = 0; q < 8; ++q) {
            float4 a = xr[q], b = ar[q];
            v[4*q+0] = a.x + b.x; v[4*q+1] = a.y + b.y;
            v[4*q+2] = a.z + b.z; v[4*q+3] = a.w + b.w;
        }
    }
    __syncthreads();                     // weights staged; both halves read agg

    // h1 for this thread's 16 outputs
    float h[16];
    #pragma unroll
    for (int oo = 0; oo < 16; ++oo) {
        const int o = obase + oo;
        float acc = sB1[o];
        const float* wr = sW1 + o * DIM;
        #pragma unroll
        for (int d = 0; d < DIM; ++d) acc = fmaf(v[d], wr[d], acc);
        h[oo] = acc;
    }

    // BN partial sums: distributed butterfly over w[32] = {s[0..15], q[0..15]}.
    // After 5 levels lane l holds the warp total of w[l].
    {
        float w[32];
        #pragma unroll
        for (int oo = 0; oo < 16; ++oo) {
            w[oo]      = h[oo];
            w[16 + oo] = h[oo] * h[oo];
        }
        #pragma unroll
        for (int lev = 0; lev < 5; ++lev) {
            const int mask = 16 >> lev;
            const int n    = 16 >> lev;
            const bool up  = (lane & mask) != 0;
            #pragma unroll
            for (int i = 0; i < n; ++i) {
                float send = up ? w[i] : w[i + n];
                float keep = up ? w[i + n] : w[i];
                w[i] = keep + __shfl_xor_sync(0xFFFFFFFFu, send, mask);
            }
        }
        // lane < 16: total s[lane]; lane >= 16: total q[lane-16]
        float* base = g_stats_part[buck];
        int idx = (lane < 16) ? (obase + lane) : (DIM + obase + (lane - 16));
        red_add_f32(base + idx, w[0]);
    }

    // ---- device-wide barrier (light fence) ----
    __threadfence();
    __syncthreads();
    if (tid == 0) {
        atomicAdd(&g_arrive, 1u);
        while (ld_acq(&g_arrive) < (unsigned)TAIL_CTAS) {}
    }
    __syncthreads();

    // agg self-clean for next replay (overlaps phase C)
    if (half == 0) {
        #pragma unroll
        for (int q = 0; q < 8; ++q) ar[q] = make_float4(0.f, 0.f, 0.f, 0.f);
    }

    // BN finalize: sum the 8 buckets (L2-hot loads, no serialization)
    if (tid < DIM) {
        float sum = 0.f, sq = 0.f;
        #pragma unroll
        for (int b = 0; b < NBUCK; ++b) {
            sum += g_stats_part[b][tid];
            sq  += g_stats_part[b][DIM + tid];
        }
        float mean = sum * (1.f / NN);
        float var  = sq * (1.f / NN) - mean * mean;
        float sc   = gamma[tid] * rsqrtf(var + BN_EPS);
        sScale[tid] = sc;
        sShift[tid] = beta[tid] - mean * sc;
        sB2[tid]    = b2[tid];
    }
    __syncthreads();

    // r = relu(BN(h)) for this half; publish to exchange buffer
    {
        float* ex = sEx + nloc * 33 + obase;
        #pragma unroll
        for (int oo = 0; oo < 16; ++oo) {
            const int o = obase + oo;
            ex[oo] = fmaxf(fmaf(h[oo], sScale[o], sShift[o]), 0.f);
        }
    }
    __syncthreads();

    // full r row for this node
    float r[DIM];
    {
        const float* ex = sEx + nloc * 33;
        #pragma unroll
        for (int d = 0; d < DIM; ++d) r[d] = ex[d];
    }

    // h2 = relu(r @ W2 + b2); distributed reduce; lanes 0-15 red into bucket
    {
        float p[16];
        #pragma unroll
        for (int oo = 0; oo < 16; ++oo) {
            const int o = obase + oo;
            float h2 = sB2[o];
            const float* wr = sW2 + o * DIM;
            #pragma unroll
            for (int d = 0; d < DIM; ++d) h2 = fmaf(r[d], wr[d], h2);
            p[oo] = fmaxf(h2, 0.f);
        }
        // standard level (mask 16): both 16-lane groups now hold identical sums
        #pragma unroll
        for (int i = 0; i < 16; ++i)
            p[i] += __shfl_xor_sync(0xFFFFFFFFu, p[i], 16);
        // distributed levels over 16 values: lane l ends with total p[l & 15]
        #pragma unroll
        for (int lev = 0; lev < 4; ++lev) {
            const int mask = 8 >> lev;
            const int n    = 8 >> lev;
            const bool up  = (lane & mask) != 0;
            #pragma unroll
            for (int i = 0; i < n; ++i) {
                float send = up ? p[i] : p[i + n];
                float keep = up ? p[i + n] : p[i];
                p[i] = keep + __shfl_xor_sync(0xFFFFFFFFu, send, mask);
            }
        }
        if (lane < 16)
            red_add_f32(g_pool_part[buck] + obase + lane, p[0]);
    }

    // ---- last CTA: reduce pool buckets, final FC, state cleanup ----
    __threadfence();
    __syncthreads();
    if (tid == 0) {
        unsigned done = atomicAdd(&g_done, 1u);
        sLast = (done == TAIL_CTAS - 1) ? 1 : 0;
    }
    __syncthreads();
    if (sLast) {
        __threadfence();
        if (tid < DIM) {
            float pl = 0.f;
            #pragma unroll
            for (int b = 0; b < NBUCK; ++b) pl += g_pool_part[b][tid];
            sPool[tid] = pl;
        }
        __syncthreads();
        if (tid < OUTD) {
            float acc = bf[tid];
            #pragma unroll
            for (int hh = 0; hh < DIM; ++hh)
                acc = fmaf(sPool[hh] * (1.f / NN), Wf[hh * OUTD + tid], acc);
            out[tid] = acc;
        }
        // zero partials + counters for the next graph replay
        for (int k = tid; k < NBUCK * 2 * DIM; k += TAIL_THREADS)
            ((float*)g_stats_part)[k] = 0.f;
        for (int k = tid; k < NBUCK * DIM; k += TAIL_THREADS)
            ((float*)g_pool_part)[k] = 0.f;
        if (tid == 0) { g_arrive = 0u; g_done = 0u; }
    }
}

extern "C" void kernel_launch(void* const* d_in, const int* in_sizes, int n_in,
                              void* d_out, int out_size)
{
    const float* x     = (const float*)d_in[0];
    const int*   adj   = (const int*)  d_in[1];
    const float* W1    = (const float*)d_in[2];
    const float* b1    = (const float*)d_in[3];
    const float* gamma = (const float*)d_in[4];
    const float* beta  = (const float*)d_in[5];
    const float* W2    = (const float*)d_in[6];
    const float* b2    = (const float*)d_in[7];
    const float* Wf    = (const float*)d_in[8];
    const float* bf    = (const float*)d_in[9];
    float* out = (float*)d_out;

    k_scan<<<SCAN_GRID, SCAN_THREADS>>>((const char*)adj, x);
    k_tail<<<TAIL_CTAS, TAIL_THREADS>>>(x, W1, b1, gamma, beta, W2, b2, Wf, bf, out);
}

// round 14
// speedup vs baseline: 1.2983x; 1.2983x over previous
#include <cuda_runtime.h>
#include <cuda_bf16.h>

#define NN 16384
#define DIM 32
#define OUTD 16
#define BN_EPS 1e-5f

#define SCAN_GRID    740          // 5 CTAs/SM x 148 SMs (keeps 28 KB L1 for x)
#define SCAN_THREADS 128
#define SCAN_WARPS   4
#define DEPTH        5            // 40 KB ring
#define STAGE_INT4   512          // 8 KB per stage
#define STAGE_BYTES  8192
#define TOTAL_STAGES 131072       // 2^26 int4 / 512

#define TAIL_CTAS    128          // <=148: co-resident, barrier-safe
#define TAIL_THREADS 256          // 2 threads per node (output split 16/16)
#define NBUCK        8            // contention-splitting factor

// Scratch (__device__ globals start zero; tail self-cleans each call)
__device__ float    g_agg[(size_t)NN * DIM];
__device__ __align__(16) float g_stats_part[NBUCK][2 * DIM]; // [b][0:32)=sum,[32:64)=sq
__device__ __align__(16) float g_pool_part[NBUCK][DIM];
__device__ unsigned g_arrive;
__device__ unsigned g_done;

// ---------------- PTX helpers ----------------
__device__ __forceinline__ unsigned smem_u32(const void* p) {
    return (unsigned)__cvta_generic_to_shared(p);
}
__device__ __forceinline__ void mbar_init(unsigned a, unsigned cnt) {
    asm volatile("mbarrier.init.shared.b64 [%0], %1;" :: "r"(a), "r"(cnt) : "memory");
}
__device__ __forceinline__ void mbar_expect_tx(unsigned a, unsigned bytes) {
    asm volatile("mbarrier.arrive.expect_tx.shared.b64 _, [%0], %1;"
                 :: "r"(a), "r"(bytes) : "memory");
}
__device__ __forceinline__ void mbar_arrive(unsigned a) {
    asm volatile("mbarrier.arrive.shared.b64 _, [%0];" :: "r"(a) : "memory");
}
__device__ __forceinline__ void mbar_wait(unsigned a, unsigned phase) {
    asm volatile(
        "{\n\t.reg .pred P;\n\t"
        "WL_%=:\n\t"
        "mbarrier.try_wait.parity.acquire.cta.shared::cta.b64 P, [%0], %1, 0x989680;\n\t"
        "@P bra.uni WD_%=;\n\t"
        "bra.uni WL_%=;\n\t"
        "WD_%=:\n\t}"
        :: "r"(a), "r"(phase) : "memory");
}
__device__ __forceinline__ void bulk_g2s(unsigned dst, const void* src,
                                         unsigned bytes, unsigned mbar) {
    asm volatile(
        "cp.async.bulk.shared::cluster.global.mbarrier::complete_tx::bytes "
        "[%0], [%1], %2, [%3];"
        :: "r"(dst), "l"(src), "r"(bytes), "r"(mbar) : "memory");
}
__device__ __forceinline__ void red_add_v4(float* p, float a, float b, float c, float d) {
    asm volatile("red.global.add.v4.f32 [%0], {%1, %2, %3, %4};"
                 :: "l"(p), "f"(a), "f"(b), "f"(c), "f"(d) : "memory");
}
__device__ __forceinline__ void red_add_f32(float* p, float a) {
    asm volatile("red.global.add.f32 [%0], %1;" :: "l"(p), "f"(a) : "memory");
}
__device__ __forceinline__ unsigned ld_acq(const unsigned* p) {
    unsigned v;
    asm volatile("ld.acquire.gpu.u32 %0, [%1];" : "=r"(v) : "l"(p) : "memory");
    return v;
}
__device__ __forceinline__ void prefetch_l2(const void* p) {
    asm volatile("prefetch.global.L2 [%0];" :: "l"(p));
}

// ---------------------------------------------------------------------------
// K1: TMA-pipelined streaming scan of adj + v4-atomic scatter of nonzeros.
// 740 CTAs = 5/SM; 200 KB smem/SM ring, 28 KB L1 retained for x hits.
// ---------------------------------------------------------------------------
__global__ __launch_bounds__(SCAN_THREADS, 5) void k_scan(
    const char*  __restrict__ Ag,
    const float* __restrict__ x)
{
    __shared__ __align__(128) int4 buf[DEPTH][STAGE_INT4];
    __shared__ __align__(8) unsigned long long mbar[2 * DEPTH];

    const int tid  = threadIdx.x;
    const int lane = tid & 31;
    const int bid  = blockIdx.x;

    unsigned mb0 = smem_u32(mbar);
    #define FULL(d)  (mb0 + (unsigned)(d) * 16u)
    #define EMPTY(d) (mb0 + (unsigned)(d) * 16u + 8u)

    if (tid == 0) {
        #pragma unroll
        for (int d = 0; d < DEPTH; ++d) {
            mbar_init(FULL(d), 1);
            mbar_init(EMPTY(d), SCAN_WARPS);
        }
    }
    __syncthreads();

    // Warm x (2 MB = 131072 float4) into L2, overlapped with ring fill
    {
        const int t = bid * SCAN_THREADS + tid;
        if (t < 65536) {
            prefetch_l2((const float4*)x + t);
            prefetch_l2((const float4*)x + t + 65536);
        }
    }

    const int cnt = (TOTAL_STAGES - bid + SCAN_GRID - 1) / SCAN_GRID;  // 177-178

    if (tid == 0) {
        int pre = cnt < DEPTH ? cnt : DEPTH;
        for (int k = 0; k < pre; ++k) {
            int s = bid + k * SCAN_GRID;
            mbar_expect_tx(FULL(k), STAGE_BYTES);
            bulk_g2s(smem_u32(buf[k]), Ag + (size_t)s * STAGE_BYTES,
                     STAGE_BYTES, FULL(k));
        }
    }

    int slot = 0;
    unsigned ph = 0;
    for (int k = 0; k < cnt; ++k) {
        mbar_wait(FULL(slot), ph);

        const unsigned s = (unsigned)(bid + k * SCAN_GRID);
        #pragma unroll
        for (int u = 0; u < 4; ++u) {
            const int idx = tid + u * SCAN_THREADS;
            int4 v = buf[slot][idx];
            if ((v.x | v.y) | (v.z | v.w)) {
                const unsigned flat = s * STAGE_INT4 + (unsigned)idx;
                const unsigned j    = flat >> 12;            // 4096 int4 per adj row
                const unsigned c4   = (flat & 4095u) << 2;   // first of 4 columns
                const float* xr = x + ((size_t)j << 5);
                const int e[4] = {v.x, v.y, v.z, v.w};
                #pragma unroll
                for (int q = 0; q < 4; ++q) {
                    if (e[q]) {
                        const float sc = (float)e[q];
                        float* ar = g_agg + ((size_t)(c4 + q) << 5);
                        #pragma unroll
                        for (int d = 0; d < DIM; d += 4) {
                            float4 xv = __ldg((const float4*)(xr + d));
                            red_add_v4(ar + d, sc * xv.x, sc * xv.y,
                                               sc * xv.z, sc * xv.w);
                        }
                    }
                }
            }
        }

        __syncwarp();
        if (lane == 0) mbar_arrive(EMPTY(slot));          // 4 arrives, not 128

        if (tid == 0 && k + DEPTH < cnt) {
            mbar_wait(EMPTY(slot), ph);
            int s2 = bid + (k + DEPTH) * SCAN_GRID;
            mbar_expect_tx(FULL(slot), STAGE_BYTES);
            bulk_g2s(smem_u32(buf[slot]), Ag + (size_t)s2 * STAGE_BYTES,
                     STAGE_BYTES, FULL(slot));
        }
        if (++slot == DEPTH) { slot = 0; ph ^= 1u; }
    }
    #undef FULL
    #undef EMPTY
}

// ---------------------------------------------------------------------------
// K2 (tail): 128 CTAs x 256 threads; node pair-split 16/16; 8-way bucketed
// global reductions via DISTRIBUTED butterfly (31 shuffles for 32 values,
// lane l ends with the total of value l) + one scalar red per lane.
// ---------------------------------------------------------------------------
__global__ __launch_bounds__(TAIL_THREADS) void k_tail(
    const float* __restrict__ x,
    const float* __restrict__ W1,
    const float* __restrict__ b1,
    const float* __restrict__ gamma,
    const float* __restrict__ beta,
    const float* __restrict__ W2,
    const float* __restrict__ b2,
    const float* __restrict__ Wf,
    const float* __restrict__ bf,
    float*       __restrict__ out)
{
    __shared__ float sW1[DIM * DIM];     // W1 transposed: [o][d]
    __shared__ float sW2[DIM * DIM];     // W2 transposed: [o][d]
    __shared__ float sB1[DIM];
    __shared__ float sScale[DIM], sShift[DIM], sB2[DIM], sPool[DIM];
    __shared__ float sEx[128 * 33];      // r-exchange between node halves
    __shared__ int   sLast;

    const int tid   = threadIdx.x;
    const int lane  = tid & 31;
    const int nloc  = tid & 127;                 // node within CTA
    const int half  = tid >> 7;                  // 0 or 1
    const int obase = half * 16;                 // this thread's output range
    const int node  = blockIdx.x * 128 + nloc;
    const int buck  = blockIdx.x & (NBUCK - 1);

    if (tid < DIM) sB1[tid] = b1[tid];
    for (int k = tid; k < DIM * DIM; k += TAIL_THREADS) {
        int d = k >> 5, o = k & 31;
        sW1[o * DIM + d] = W1[k];
        sW2[o * DIM + d] = W2[k];
    }

    // v = x[node] + agg[node] -- both halves read; zeroing deferred
    float v[DIM];
    float4* ar = (float4*)(g_agg + ((size_t)node << 5));
    {
        const float4* xr = (const float4*)(x + ((size_t)node << 5));
        #pragma unroll
        for (int q = 0; q < 8; ++q) {
            float4 a = xr[q], b = ar[q];
            v[4*q+0] = a.x + b.x; v[4*q+1] = a.y + b.y;
            v[4*q+2] = a.z + b.z; v[4*q+3] = a.w + b.w;
        }
    }
    __syncthreads();                     // weights staged; both halves read agg

    // h1 for this thread's 16 outputs
    float h[16];
    #pragma unroll
    for (int oo = 0; oo < 16; ++oo) {
        const int o = obase + oo;
        float acc = sB1[o];
        const float* wr = sW1 + o * DIM;
        #pragma unroll
        for (int d = 0; d < DIM; ++d) acc = fmaf(v[d], wr[d], acc);
        h[oo] = acc;
    }

    // BN partial sums: distributed butterfly over w[32] = {s[0..15], q[0..15]}.
    // After 5 levels lane l holds the warp total of w[l].
    {
        float w[32];
        #pragma unroll
        for (int oo = 0; oo < 16; ++oo) {
            w[oo]      = h[oo];
            w[16 + oo] = h[oo] * h[oo];
        }
        #pragma unroll
        for (int lev = 0; lev < 5; ++lev) {
            const int mask = 16 >> lev;
            const int n    = 16 >> lev;
            const bool up  = (lane & mask) != 0;
            #pragma unroll
            for (int i = 0; i < n; ++i) {
                float send = up ? w[i] : w[i + n];
                float keep = up ? w[i + n] : w[i];
                w[i] = keep + __shfl_xor_sync(0xFFFFFFFFu, send, mask);
            }
        }
        // lane < 16: total s[lane]; lane >= 16: total q[lane-16]
        float* base = g_stats_part[buck];
        int idx = (lane < 16) ? (obase + lane) : (DIM + obase + (lane - 16));
        red_add_f32(base + idx, w[0]);
    }

    // ---- device-wide barrier (light fence) ----
    __threadfence();
    __syncthreads();
    if (tid == 0) {
        atomicAdd(&g_arrive, 1u);
        while (ld_acq(&g_arrive) < (unsigned)TAIL_CTAS) {}
    }
    __syncthreads();

    // agg self-clean for next replay (overlaps phase C)
    if (half == 0) {
        #pragma unroll
        for (int q = 0; q < 8; ++q) ar[q] = make_float4(0.f, 0.f, 0.f, 0.f);
    }

    // BN finalize: sum the 8 buckets (L2-hot loads, no serialization)
    if (tid < DIM) {
        float sum = 0.f, sq = 0.f;
        #pragma unroll
        for (int b = 0; b < NBUCK; ++b) {
            sum += g_stats_part[b][tid];
            sq  += g_stats_part[b][DIM + tid];
        }
        float mean = sum * (1.f / NN);
        float var  = sq * (1.f / NN) - mean * mean;
        float sc   = gamma[tid] * rsqrtf(var + BN_EPS);
        sScale[tid] = sc;
        sShift[tid] = beta[tid] - mean * sc;
        sB2[tid]    = b2[tid];
    }
    __syncthreads();

    // r = relu(BN(h)) for this half; publish to exchange buffer
    {
        float* ex = sEx + nloc * 33 + obase;
        #pragma unroll
        for (int oo = 0; oo < 16; ++oo) {
            const int o = obase + oo;
            ex[oo] = fmaxf(fmaf(h[oo], sScale[o], sShift[o]), 0.f);
        }
    }
    __syncthreads();

    // full r row for this node
    float r[DIM];
    {
        const float* ex = sEx + nloc * 33;
        #pragma unroll
        for (int d = 0; d < DIM; ++d) r[d] = ex[d];
    }

    // h2 = relu(r @ W2 + b2); distributed reduce; lanes 0-15 red into bucket
    {
        float p[16];
        #pragma unroll
        for (int oo = 0; oo < 16; ++oo) {
            const int o = obase + oo;
            float h2 = sB2[o];
            const float* wr = sW2 + o * DIM;
            #pragma unroll
            for (int d = 0; d < DIM; ++d) h2 = fmaf(r[d], wr[d], h2);
            p[oo] = fmaxf(h2, 0.f);
        }
        // standard level (mask 16): both 16-lane groups now hold identical sums
        #pragma unroll
        for (int i = 0; i < 16; ++i)
            p[i] += __shfl_xor_sync(0xFFFFFFFFu, p[i], 16);
        // distributed levels over 16 values: lane l ends with total p[l & 15]
        #pragma unroll
        for (int lev = 0; lev < 4; ++lev) {
            const int mask = 8 >> lev;
            const int n    = 8 >> lev;
            const bool up  = (lane & mask) != 0;
            #pragma unroll
            for (int i = 0; i < n; ++i) {
                float send = up ? p[i] : p[i + n];
                float keep = up ? p[i + n] : p[i];
                p[i] = keep + __shfl_xor_sync(0xFFFFFFFFu, send, mask);
            }
        }
        if (lane < 16)
            red_add_f32(g_pool_part[buck] + obase + lane, p[0]);
    }

    // ---- last CTA: reduce pool buckets, final FC, state cleanup ----
    __threadfence();
    __syncthreads();
    if (tid == 0) {
        unsigned done = atomicAdd(&g_done, 1u);
        sLast = (done == TAIL_CTAS - 1) ? 1 : 0;
    }
    __syncthreads();
    if (sLast) {
        __threadfence();
        if (tid < DIM) {
            float pl = 0.f;
            #pragma unroll
            for (int b = 0; b < NBUCK; ++b) pl += g_pool_part[b][tid];
            sPool[tid] = pl;
        }
        __syncthreads();
        if (tid < OUTD) {
            float acc = bf[tid];
            #pragma unroll
            for (int hh = 0; hh < DIM; ++hh)
                acc = fmaf(sPool[hh] * (1.f / NN), Wf[hh * OUTD + tid], acc);
            out[tid] = acc;
        }
        // zero partials + counters for the next graph replay
        for (int k = tid; k < NBUCK * 2 * DIM; k += TAIL_THREADS)
            ((float*)g_stats_part)[k] = 0.f;
        for (int k = tid; k < NBUCK * DIM; k += TAIL_THREADS)
            ((float*)g_pool_part)[k] = 0.f;
        if (tid == 0) { g_arrive = 0u; g_done = 0u; }
    }
}

extern "C" void kernel_launch(void* const* d_in, const int* in_sizes, int n_in,
                              void* d_out, int out_size)
{
    const float* x     = (const float*)d_in[0];
    const int*   adj   = (const int*)  d_in[1];
    const float* W1    = (const float*)d_in[2];
    const float* b1    = (const float*)d_in[3];
    const float* gamma = (const float*)d_in[4];
    const float* beta  = (const float*)d_in[5];
    const float* W2    = (const float*)d_in[6];
    const float* b2    = (const float*)d_in[7];
    const float* Wf    = (const float*)d_in[8];
    const float* bf    = (const float*)d_in[9];
    float* out = (float*)d_out;

    k_scan<<<SCAN_GRID, SCAN_THREADS>>>((const char*)adj, x);
    k_tail<<<TAIL_CTAS, TAIL_THREADS>>>(x, W1, b1, gamma, beta, W2, b2, Wf, bf, out);
}